// round 1
// baseline (speedup 1.0000x reference)
#include <cuda_runtime.h>
#include <cstdint>

// Problem constants
constexpr int B_  = 8192;
constexpr int T_  = 658;
constexpr int I_  = 7;
constexpr int D1_ = 1024;
constexpr int D2_ = 512;
constexpr int D3_ = 128;
constexpr int XWT = 688;   // T_ padded to 43*16 for scan prefetch overrun

// Scratch (device globals are zero-initialized; pad region of g_xw stays 0)
__device__ float g_xw[(size_t)XWT * B_];
__device__ float g_hs[(size_t)T_  * B_];
__device__ float g_y1[(size_t)B_ * D1_];
__device__ float g_y2[(size_t)B_ * D2_];
__device__ float g_y3[(size_t)B_ * D3_];

// ---------------------------------------------------------------------------
// Stage 1: xw[t,b] = dot(x[b,t,:], W_ih) + b_ih + b_hh   (stored [T,B])
// ---------------------------------------------------------------------------
__global__ void proj_kernel(const float* __restrict__ x,
                            const float* __restrict__ W_ih,
                            const float* __restrict__ b_ih,
                            const float* __restrict__ b_hh) {
    __shared__ float xs[32][225];  // 32 b-rows x (32 t * 7), pad 225 for bank-free compute
    const int t0  = blockIdx.x * 32;
    const int b0  = blockIdx.y * 32;
    const int tid = threadIdx.x;
    const int tlim = min(32, T_ - t0);
    const int nfl  = tlim * I_;

    // Coalesced load: each b-row is a contiguous 224-float chunk of x
    for (int i = tid; i < 32 * 224; i += 256) {
        int bl  = i / 224;
        int off = i - bl * 224;
        float v = 0.f;
        if (off < nfl)
            v = x[((size_t)(b0 + bl) * T_ + t0) * I_ + off];
        xs[bl][off] = v;
    }
    __syncthreads();

    float w[7];
#pragma unroll
    for (int j = 0; j < 7; ++j) w[j] = W_ih[j];
    const float bias = b_ih[0] + b_hh[0];

    // Coalesced transposed store: adjacent threads -> adjacent b
    for (int i = tid; i < 1024; i += 256) {
        int bl = i & 31;
        int tl = i >> 5;
        if (tl < tlim) {
            const float* row = &xs[bl][tl * 7];
            float s = bias;
#pragma unroll
            for (int j = 0; j < 7; ++j) s = fmaf(row[j], w[j], s);
            g_xw[(size_t)(t0 + tl) * B_ + (b0 + bl)] = s;
        }
    }
}

// ---------------------------------------------------------------------------
// Stage 2: scalar tanh recurrence, one thread per batch element
// ---------------------------------------------------------------------------
__device__ __forceinline__ float tanh_fast(float xv) {
    float ax = fabsf(xv);
    float e  = __expf(-2.0f * ax);          // MUFU.EX2 path, ~1e-7 rel err
    float r  = __fdividef(1.0f - e, 1.0f + e);
    return copysignf(r, xv);
}

__global__ void scan_kernel(const float* __restrict__ h0,
                            const float* __restrict__ W_hh) {
    const int b = blockIdx.x * blockDim.x + threadIdx.x;
    if (b >= B_) return;
    const float whh = W_hh[0];
    const float* xp = g_xw + b;
    float* hp = g_hs + b;
    float h = h0[b];

    float bufA[16], bufB[16];
#pragma unroll
    for (int j = 0; j < 16; ++j) bufA[j] = xp[(size_t)j * B_];

    for (int tc = 0; tc < 672; tc += 32) {
        // Prefetch next 16 while chewing on bufA (chain: FFMA+EX2+RCP ~50cyc/step)
#pragma unroll
        for (int j = 0; j < 16; ++j) bufB[j] = xp[(size_t)(tc + 16 + j) * B_];
#pragma unroll
        for (int j = 0; j < 16; ++j) {
            h = tanh_fast(fmaf(h, whh, bufA[j]));
            int t = tc + j;
            if (t < T_) hp[(size_t)t * B_] = h;
        }
#pragma unroll
        for (int j = 0; j < 16; ++j) bufA[j] = xp[(size_t)(tc + 32 + j) * B_]; // max idx 687 < XWT
#pragma unroll
        for (int j = 0; j < 16; ++j) {
            h = tanh_fast(fmaf(h, whh, bufB[j]));
            int t = tc + 16 + j;
            if (t < T_) hp[(size_t)t * B_] = h;
        }
    }
}

// ---------------------------------------------------------------------------
// Stages 3-6: C[m,n] = act( sum_k A(m,k) * W[n*K+k] + bias[n] )
//   TRANS_A: A stored [K,M] (used for hs which is [T,B])
// 128x128x16 tile, 256 threads, 8x8 microtile.
// ---------------------------------------------------------------------------
template <bool TRANS_A, bool DO_RELU>
__global__ void gemm_bias(const float* __restrict__ A,
                          const float* __restrict__ W,
                          const float* __restrict__ bias,
                          float* __restrict__ C,
                          int M, int N, int K) {
    constexpr int BM = 128, BN = 128, BK = 16;
    __shared__ float As[BK][BM + 4];
    __shared__ float Bs[BK][BN + 4];

    const int bm  = blockIdx.x * BM;
    const int bn  = blockIdx.y * BN;
    const int tid = threadIdx.x;
    const int tr  = (tid >> 4) * 8;   // 0..120
    const int tc  = (tid & 15) * 8;

    float acc[8][8];
#pragma unroll
    for (int i = 0; i < 8; ++i)
#pragma unroll
        for (int j = 0; j < 8; ++j) acc[i][j] = 0.f;

    for (int k0 = 0; k0 < K; k0 += BK) {
        // --- load A tile ---
#pragma unroll
        for (int r = 0; r < (BM * BK) / 256; ++r) {
            int lin = tid + r * 256;
            if (TRANS_A) {
                int m = lin & 127, k = lin >> 7;
                int gk = k0 + k;
                float v = 0.f;
                if (gk < K) v = A[(size_t)gk * M + (bm + m)];
                As[k][m] = v;
            } else {
                int k = lin & 15, m = lin >> 4;
                int gk = k0 + k;
                float v = 0.f;
                if (gk < K) v = A[(size_t)(bm + m) * K + gk];
                As[k][m] = v;
            }
        }
        // --- load W tile -> Bs[k][n] ---
#pragma unroll
        for (int r = 0; r < (BN * BK) / 256; ++r) {
            int lin = tid + r * 256;
            int k = lin & 15, n = lin >> 4;
            int gk = k0 + k, gn = bn + n;
            float v = 0.f;
            if (gk < K && gn < N) v = W[(size_t)gn * K + gk];
            Bs[k][n] = v;
        }
        __syncthreads();

#pragma unroll
        for (int kk = 0; kk < BK; ++kk) {
            float a[8], bfr[8];
#pragma unroll
            for (int i = 0; i < 8; ++i) a[i] = As[kk][tr + i];
#pragma unroll
            for (int j = 0; j < 8; ++j) bfr[j] = Bs[kk][tc + j];
#pragma unroll
            for (int i = 0; i < 8; ++i)
#pragma unroll
                for (int j = 0; j < 8; ++j)
                    acc[i][j] = fmaf(a[i], bfr[j], acc[i][j]);
        }
        __syncthreads();
    }

    // epilogue: bias (+ relu)
#pragma unroll
    for (int i = 0; i < 8; ++i) {
        int gm = bm + tr + i;
        if (gm >= M) continue;
#pragma unroll
        for (int j = 0; j < 8; ++j) {
            int gn = bn + tc + j;
            if (gn < N) {
                float v = acc[i][j] + bias[gn];
                if (DO_RELU) v = fmaxf(v, 0.f);
                C[(size_t)gm * N + gn] = v;
            }
        }
    }
}

// ---------------------------------------------------------------------------
// Stage 7: hidden output = hs[T-1, :]
// ---------------------------------------------------------------------------
__global__ void copy_hidden(float* __restrict__ dst) {
    int i = blockIdx.x * blockDim.x + threadIdx.x;
    if (i < B_) dst[i] = g_hs[(size_t)(T_ - 1) * B_ + i];
}

// ---------------------------------------------------------------------------
extern "C" void kernel_launch(void* const* d_in, const int* in_sizes, int n_in,
                              void* d_out, int out_size) {
    const float* x    = (const float*)d_in[0];
    const float* h0   = (const float*)d_in[1];
    const float* W_ih = (const float*)d_in[2];
    const float* W_hh = (const float*)d_in[3];
    const float* b_ih = (const float*)d_in[4];
    const float* b_hh = (const float*)d_in[5];
    const float* w1   = (const float*)d_in[6];
    const float* b1   = (const float*)d_in[7];
    const float* w2   = (const float*)d_in[8];
    const float* b2   = (const float*)d_in[9];
    const float* w3   = (const float*)d_in[10];
    const float* b3   = (const float*)d_in[11];
    const float* w4   = (const float*)d_in[12];
    const float* b4   = (const float*)d_in[13];
    float* out = (float*)d_out;

    float *hs_p, *y1_p, *y2_p, *y3_p;
    cudaGetSymbolAddress((void**)&hs_p, g_hs);
    cudaGetSymbolAddress((void**)&y1_p, g_y1);
    cudaGetSymbolAddress((void**)&y2_p, g_y2);
    cudaGetSymbolAddress((void**)&y3_p, g_y3);

    // 1) input projection  [T,B]
    proj_kernel<<<dim3((T_ + 31) / 32, B_ / 32), 256>>>(x, W_ih, b_ih, b_hh);
    // 2) recurrence -> hs [T,B]
    scan_kernel<<<B_ / 128, 128>>>(h0, W_hh);
    // 3) y1 = relu(hs^T @ w1^T + b1)   M=B, N=1024, K=658, A transposed-layout
    gemm_bias<true,  true ><<<dim3(B_ / 128, D1_ / 128), 256>>>(hs_p, w1, b1, y1_p, B_, D1_, T_);
    // 4) y2 = relu(y1 @ w2^T + b2)
    gemm_bias<false, true ><<<dim3(B_ / 128, D2_ / 128), 256>>>(y1_p, w2, b2, y2_p, B_, D2_, D1_);
    // 5) y3 = relu(y2 @ w3^T + b3)
    gemm_bias<false, true ><<<dim3(B_ / 128, D3_ / 128), 256>>>(y2_p, w3, b3, y3_p, B_, D3_, D2_);
    // 6) out = y3 @ w4^T + b4   (N=658, ragged)
    gemm_bias<false, false><<<dim3(B_ / 128, (T_ + 127) / 128), 256>>>(y3_p, w4, b4, out, B_, T_, D3_);
    // 7) hidden state output (if harness expects both tuple outputs)
    if (out_size >= B_ * T_ + B_)
        copy_hidden<<<B_ / 256, 256>>>(out + (size_t)B_ * T_);
}

// round 4
// speedup vs baseline: 2.3882x; 2.3882x over previous
#include <cuda_runtime.h>
#include <cuda_bf16.h>
#include <cstdint>

// ---------------------------------------------------------------------------
// Problem constants
// ---------------------------------------------------------------------------
constexpr int B_   = 8192;
constexpr int T_   = 658;
constexpr int I_   = 7;
constexpr int D1_  = 1024;
constexpr int D2_  = 512;
constexpr int D3_  = 128;
constexpr int XWT  = 688;            // T_ padded for scan prefetch overrun
constexpr int TPAD = 672;            // T_ padded to multiple of 32 (GEMM1 K)

// ---------------------------------------------------------------------------
// Scratch (device globals zero-init; padded regions either rewritten or 0)
// ---------------------------------------------------------------------------
__device__ float          g_xw [(size_t)XWT * B_];
__device__ float          g_hs [(size_t)T_  * B_];     // [T,B] fp32
__device__ __nv_bfloat16  g_ath[(size_t)B_ * TPAD];    // hs^T hi  [B,TPAD]
__device__ __nv_bfloat16  g_atl[(size_t)B_ * TPAD];    // hs^T lo

__device__ __nv_bfloat16  g_w1h[(size_t)D1_ * TPAD], g_w1l[(size_t)D1_ * TPAD];
__device__ __nv_bfloat16  g_w2h[(size_t)D2_ * D1_ ], g_w2l[(size_t)D2_ * D1_ ];
__device__ __nv_bfloat16  g_w3h[(size_t)D3_ * D2_ ], g_w3l[(size_t)D3_ * D2_ ];
__device__ __nv_bfloat16  g_w4h[(size_t)T_  * D3_ ], g_w4l[(size_t)T_  * D3_ ];

__device__ __nv_bfloat16  g_y1h[(size_t)B_ * D1_], g_y1l[(size_t)B_ * D1_];
__device__ __nv_bfloat16  g_y2h[(size_t)B_ * D2_], g_y2l[(size_t)B_ * D2_];
__device__ __nv_bfloat16  g_y3h[(size_t)B_ * D3_], g_y3l[(size_t)B_ * D3_];

// ---------------------------------------------------------------------------
// PTX helpers (base-target ISA only: ldmatrix / mma.sync / cp.async)
// ---------------------------------------------------------------------------
__device__ __forceinline__ uint32_t smem_u32(const void* p) {
    uint32_t a;
    asm("{ .reg .u64 t; cvta.to.shared.u64 t, %1; cvt.u32.u64 %0, t; }" : "=r"(a) : "l"(p));
    return a;
}

__device__ __forceinline__ void cp16(uint32_t dst, const void* src, int srcsize) {
    asm volatile("cp.async.cg.shared.global [%0], [%1], 16, %2;"
                 :: "r"(dst), "l"(src), "r"(srcsize));
}
#define CP_COMMIT() asm volatile("cp.async.commit_group;" ::: "memory")
#define CP_WAIT(n)  asm volatile("cp.async.wait_group %0;" :: "n"(n) : "memory")

#define LDSM4(r, a)                                                             \
    asm volatile("ldmatrix.sync.aligned.m8n8.x4.shared.b16 {%0,%1,%2,%3}, [%4];"\
                 : "=r"((r)[0]), "=r"((r)[1]), "=r"((r)[2]), "=r"((r)[3])       \
                 : "r"(a))

__device__ __forceinline__ void mma16816(float* d, const uint32_t* a,
                                         uint32_t b0, uint32_t b1) {
    asm volatile("mma.sync.aligned.m16n8k16.row.col.f32.bf16.bf16.f32 "
                 "{%0,%1,%2,%3}, {%4,%5,%6,%7}, {%8,%9}, {%0,%1,%2,%3};"
                 : "+f"(d[0]), "+f"(d[1]), "+f"(d[2]), "+f"(d[3])
                 : "r"(a[0]), "r"(a[1]), "r"(a[2]), "r"(a[3]), "r"(b0), "r"(b1));
}

// ---------------------------------------------------------------------------
// Stage 1: xw[t,b] = dot(x[b,t,:], W_ih) + b_ih + b_hh   ([T,B] fp32)
// ---------------------------------------------------------------------------
__global__ void proj_kernel(const float* __restrict__ x,
                            const float* __restrict__ W_ih,
                            const float* __restrict__ b_ih,
                            const float* __restrict__ b_hh) {
    __shared__ float xs[32][225];
    const int t0 = blockIdx.x * 32;
    const int b0 = blockIdx.y * 32;
    const int tid = threadIdx.x;
    const int tlim = min(32, T_ - t0);
    const int nfl = tlim * I_;

    for (int i = tid; i < 32 * 224; i += 256) {
        int bl = i / 224;
        int off = i - bl * 224;
        float v = 0.f;
        if (off < nfl) v = x[((size_t)(b0 + bl) * T_ + t0) * I_ + off];
        xs[bl][off] = v;
    }
    __syncthreads();

    float w[7];
#pragma unroll
    for (int j = 0; j < 7; ++j) w[j] = W_ih[j];
    const float bias = b_ih[0] + b_hh[0];

    for (int i = tid; i < 1024; i += 256) {
        int bl = i & 31;
        int tl = i >> 5;
        if (tl < tlim) {
            const float* row = &xs[bl][tl * 7];
            float s = bias;
#pragma unroll
            for (int j = 0; j < 7; ++j) s = fmaf(row[j], w[j], s);
            g_xw[(size_t)(t0 + tl) * B_ + (b0 + bl)] = s;
        }
    }
}

// ---------------------------------------------------------------------------
// Stage 2: scalar tanh recurrence -> g_hs [T,B] fp32, hidden -> hid
//   NOTE: loop runs to t=671 (padding); hidden state must be the value at
//   t == T_-1, NOT the loop-exit value (pad steps contaminate h).
// ---------------------------------------------------------------------------
__device__ __forceinline__ float tanh_fast(float xv) {
    float ax = fabsf(xv);
    float e = __expf(-2.0f * ax);
    float r = __fdividef(1.0f - e, 1.0f + e);
    return copysignf(r, xv);
}

__global__ void scan_kernel(const float* __restrict__ h0,
                            const float* __restrict__ W_hh,
                            float* __restrict__ hid) {
    const int b = blockIdx.x * blockDim.x + threadIdx.x;
    if (b >= B_) return;
    const float whh = W_hh[0];
    const float* xp = g_xw + b;
    float* hp = g_hs + b;
    float h = h0[b];
    float hT = h;

    float bufA[16], bufB[16];
#pragma unroll
    for (int j = 0; j < 16; ++j) bufA[j] = xp[(size_t)j * B_];

    for (int tc = 0; tc < 672; tc += 32) {
#pragma unroll
        for (int j = 0; j < 16; ++j) bufB[j] = xp[(size_t)(tc + 16 + j) * B_];
#pragma unroll
        for (int j = 0; j < 16; ++j) {
            h = tanh_fast(fmaf(h, whh, bufA[j]));
            int t = tc + j;
            if (t < T_) hp[(size_t)t * B_] = h;
            if (t == T_ - 1) hT = h;
        }
#pragma unroll
        for (int j = 0; j < 16; ++j) bufA[j] = xp[(size_t)(tc + 32 + j) * B_];
#pragma unroll
        for (int j = 0; j < 16; ++j) {
            h = tanh_fast(fmaf(h, whh, bufB[j]));
            int t = tc + 16 + j;
            if (t < T_) hp[(size_t)t * B_] = h;
            if (t == T_ - 1) hT = h;
        }
    }
    if (hid) hid[b] = hT;
}

// ---------------------------------------------------------------------------
// Stage 3: transpose+convert  g_hs[T,B] fp32  ->  g_ath/g_atl [B,TPAD] bf16
// ---------------------------------------------------------------------------
__global__ void transpose_hs() {
    __shared__ float s[32][33];
    const int t0 = blockIdx.x * 32;
    const int b0 = blockIdx.y * 32;
    const int tx = threadIdx.x & 31;
    const int ty = threadIdx.x >> 5;   // 0..7

#pragma unroll
    for (int r = 0; r < 4; ++r) {
        int t = t0 + ty + r * 8;
        s[ty + r * 8][tx] = (t < T_) ? g_hs[(size_t)t * B_ + b0 + tx] : 0.f;
    }
    __syncthreads();

#pragma unroll
    for (int r = 0; r < 4; ++r) {
        int bl = ty + r * 8;
        float v = s[tx][bl];
        __nv_bfloat16 hv = __float2bfloat16(v);
        __nv_bfloat16 lv = __float2bfloat16(v - __bfloat162float(hv));
        size_t o = (size_t)(b0 + bl) * TPAD + t0 + tx;
        g_ath[o] = hv;
        g_atl[o] = lv;
    }
}

// ---------------------------------------------------------------------------
// Weight conversion: fp32 [R,K] -> bf16 hi/lo [R,Kp] (pad stays 0)
// ---------------------------------------------------------------------------
__global__ void cvt_w(const float* __restrict__ src,
                      __nv_bfloat16* __restrict__ hi,
                      __nv_bfloat16* __restrict__ lo,
                      int R, int K, int Kp) {
    int i = blockIdx.x * blockDim.x + threadIdx.x;
    if (i < R * K) {
        int r = i / K, k = i - r * K;
        float v = src[i];
        __nv_bfloat16 h = __float2bfloat16(v);
        hi[(size_t)r * Kp + k] = h;
        lo[(size_t)r * Kp + k] = __float2bfloat16(v - __bfloat162float(h));
    }
}

// ---------------------------------------------------------------------------
// mma.sync GEMM: C[M,N] = act(A * B^T + bias), 3-term bf16 hi/lo split.
//   A: [M,K] bf16 hi/lo row-major.  B: [N,K] bf16 hi/lo K-major.
//   CTA 128x128, BK=32, cp.async double buffer, warp tile 32x64.
// ---------------------------------------------------------------------------
constexpr int PITCH = 80;
constexpr int MATSZ = 128 * PITCH;        // 10240
constexpr int STAGE = 4 * MATSZ;          // 40960
constexpr int GEMM_SMEM = 2 * STAGE;      // 81920

__device__ __forceinline__ void load_stage(
        uint32_t sbase, int stage, int k0, int tid,
        const __nv_bfloat16* Ah, const __nv_bfloat16* Al,
        const __nv_bfloat16* Bh, const __nv_bfloat16* Bl,
        int K, int N, int bm, int bn) {
#pragma unroll
    for (int it = 0; it < 8; ++it) {
        int i = tid + it * 256;
        int mat = i >> 9;          // 0:Ah 1:Al 2:Bh 3:Bl
        int row = (i >> 2) & 127;
        int seg = i & 3;
        uint32_t dst = sbase + stage * STAGE + mat * MATSZ + row * PITCH + seg * 16;
        const __nv_bfloat16* src;
        int size = 16;
        if (mat < 2) {
            src = (mat == 0 ? Ah : Al) + (size_t)(bm + row) * K + k0 + seg * 8;
        } else {
            const __nv_bfloat16* base = (mat == 2 ? Bh : Bl);
            int n = bn + row;
            if (n < N) {
                src = base + (size_t)n * K + k0 + seg * 8;
            } else {
                src = base + k0 + seg * 8;
                size = 0;
            }
        }
        cp16(dst, src, size);
    }
}

template <bool RELU, bool F32OUT>
__global__ void __launch_bounds__(256)
gemm_mma(const __nv_bfloat16* __restrict__ Ah, const __nv_bfloat16* __restrict__ Al,
         const __nv_bfloat16* __restrict__ Bh, const __nv_bfloat16* __restrict__ Bl,
         const float* __restrict__ bias,
         __nv_bfloat16* __restrict__ Oh, __nv_bfloat16* __restrict__ Ol,
         float* __restrict__ Of,
         int K, int N, int strideO) {
    extern __shared__ char smem[];
    const uint32_t sbase = smem_u32(smem);
    const int tid = threadIdx.x;
    const int lane = tid & 31;
    const int wid = tid >> 5;
    const int wm = wid & 3;         // 4 warps over M
    const int wn = wid >> 2;        // 2 warps over N
    const int bm = blockIdx.x * 128;
    const int bn = blockIdx.y * 128;
    const int nk = K >> 5;

    float acc[2][8][4];
#pragma unroll
    for (int i = 0; i < 2; ++i)
#pragma unroll
        for (int j = 0; j < 8; ++j)
#pragma unroll
            for (int q = 0; q < 4; ++q) acc[i][j][q] = 0.f;

    const uint32_t a_addr = sbase + (wm * 32 + (lane & 15)) * PITCH + (lane >> 4) * 16;
    const uint32_t b_addr = sbase + 2 * MATSZ +
        (wn * 64 + (lane & 7) + ((lane >> 4) * 8)) * PITCH + ((lane >> 3) & 1) * 16;

    load_stage(sbase, 0, 0, tid, Ah, Al, Bh, Bl, K, N, bm, bn);
    CP_COMMIT();

    for (int kc = 0; kc < nk; ++kc) {
        __syncthreads();
        if (kc + 1 < nk) {
            load_stage(sbase, (kc + 1) & 1, (kc + 1) * 32, tid, Ah, Al, Bh, Bl, K, N, bm, bn);
            CP_COMMIT();
            CP_WAIT(1);
        } else {
            CP_WAIT(0);
        }
        __syncthreads();

        const uint32_t st = ((kc & 1) ? STAGE : 0);
#pragma unroll
        for (int kk = 0; kk < 2; ++kk) {
            const uint32_t ko = kk * 32;
            uint32_t aH[2][4], aL[2][4];
#pragma unroll
            for (int mi = 0; mi < 2; ++mi) {
                LDSM4(aH[mi], a_addr + st + mi * (16 * PITCH) + ko);
                LDSM4(aL[mi], a_addr + st + MATSZ + mi * (16 * PITCH) + ko);
            }
            uint32_t bH[4][4], bL[4][4];
#pragma unroll
            for (int np = 0; np < 4; ++np) {
                LDSM4(bH[np], b_addr + st + np * (16 * PITCH) + ko);
                LDSM4(bL[np], b_addr + st + MATSZ + np * (16 * PITCH) + ko);
            }
#pragma unroll
            for (int mi = 0; mi < 2; ++mi)
#pragma unroll
                for (int np = 0; np < 4; ++np) {
                    float* d0 = acc[mi][np * 2];
                    float* d1 = acc[mi][np * 2 + 1];
                    mma16816(d0, aH[mi], bH[np][0], bH[np][1]);
                    mma16816(d0, aH[mi], bL[np][0], bL[np][1]);
                    mma16816(d0, aL[mi], bH[np][0], bH[np][1]);
                    mma16816(d1, aH[mi], bH[np][2], bH[np][3]);
                    mma16816(d1, aH[mi], bL[np][2], bL[np][3]);
                    mma16816(d1, aL[mi], bH[np][2], bH[np][3]);
                }
        }
    }

    // Epilogue
    const int g = lane >> 2, tig = lane & 3;
#pragma unroll
    for (int mi = 0; mi < 2; ++mi) {
#pragma unroll
        for (int np = 0; np < 4; ++np) {
#pragma unroll
            for (int c = 0; c < 2; ++c) {
                int col = bn + wn * 64 + np * 16 + c * 8 + 2 * tig;
                float b0 = 0.f, b1 = 0.f;
                if (col < N) { b0 = bias[col]; b1 = bias[col + 1]; }
                float* a = acc[mi][np * 2 + c];
                int r0 = bm + wm * 32 + mi * 16 + g;
                float v00 = a[0] + b0, v01 = a[1] + b1;
                float v10 = a[2] + b0, v11 = a[3] + b1;
                if (RELU) {
                    v00 = fmaxf(v00, 0.f); v01 = fmaxf(v01, 0.f);
                    v10 = fmaxf(v10, 0.f); v11 = fmaxf(v11, 0.f);
                }
                if (F32OUT) {
                    if (col < N) {
                        *(float2*)(Of + (size_t)r0 * strideO + col) = make_float2(v00, v01);
                        *(float2*)(Of + (size_t)(r0 + 8) * strideO + col) = make_float2(v10, v11);
                    }
                } else {
                    __nv_bfloat16 h00 = __float2bfloat16(v00), h01 = __float2bfloat16(v01);
                    __nv_bfloat16 h10 = __float2bfloat16(v10), h11 = __float2bfloat16(v11);
                    __nv_bfloat16 l00 = __float2bfloat16(v00 - __bfloat162float(h00));
                    __nv_bfloat16 l01 = __float2bfloat16(v01 - __bfloat162float(h01));
                    __nv_bfloat16 l10 = __float2bfloat16(v10 - __bfloat162float(h10));
                    __nv_bfloat16 l11 = __float2bfloat16(v11 - __bfloat162float(h11));
                    uint32_t ph0 = (uint32_t)__bfloat16_as_ushort(h00) | ((uint32_t)__bfloat16_as_ushort(h01) << 16);
                    uint32_t pl0 = (uint32_t)__bfloat16_as_ushort(l00) | ((uint32_t)__bfloat16_as_ushort(l01) << 16);
                    uint32_t ph1 = (uint32_t)__bfloat16_as_ushort(h10) | ((uint32_t)__bfloat16_as_ushort(h11) << 16);
                    uint32_t pl1 = (uint32_t)__bfloat16_as_ushort(l10) | ((uint32_t)__bfloat16_as_ushort(l11) << 16);
                    *(uint32_t*)(Oh + (size_t)r0 * strideO + col) = ph0;
                    *(uint32_t*)(Ol + (size_t)r0 * strideO + col) = pl0;
                    *(uint32_t*)(Oh + (size_t)(r0 + 8) * strideO + col) = ph1;
                    *(uint32_t*)(Ol + (size_t)(r0 + 8) * strideO + col) = pl1;
                }
            }
        }
    }
}

// ---------------------------------------------------------------------------
extern "C" void kernel_launch(void* const* d_in, const int* in_sizes, int n_in,
                              void* d_out, int out_size) {
    const float* x    = (const float*)d_in[0];
    const float* h0   = (const float*)d_in[1];
    const float* W_ih = (const float*)d_in[2];
    const float* W_hh = (const float*)d_in[3];
    const float* b_ih = (const float*)d_in[4];
    const float* b_hh = (const float*)d_in[5];
    const float* w1   = (const float*)d_in[6];
    const float* b1   = (const float*)d_in[7];
    const float* w2   = (const float*)d_in[8];
    const float* b2   = (const float*)d_in[9];
    const float* w3   = (const float*)d_in[10];
    const float* b3   = (const float*)d_in[11];
    const float* w4   = (const float*)d_in[12];
    const float* b4   = (const float*)d_in[13];
    float* out = (float*)d_out;
    float* hid = (out_size >= B_ * T_ + B_) ? out + (size_t)B_ * T_ : nullptr;

    __nv_bfloat16 *ath, *atl, *w1h, *w1l, *w2h, *w2l, *w3h, *w3l, *w4h, *w4l;
    __nv_bfloat16 *y1h, *y1l, *y2h, *y2l, *y3h, *y3l;
    cudaGetSymbolAddress((void**)&ath, g_ath); cudaGetSymbolAddress((void**)&atl, g_atl);
    cudaGetSymbolAddress((void**)&w1h, g_w1h); cudaGetSymbolAddress((void**)&w1l, g_w1l);
    cudaGetSymbolAddress((void**)&w2h, g_w2h); cudaGetSymbolAddress((void**)&w2l, g_w2l);
    cudaGetSymbolAddress((void**)&w3h, g_w3h); cudaGetSymbolAddress((void**)&w3l, g_w3l);
    cudaGetSymbolAddress((void**)&w4h, g_w4h); cudaGetSymbolAddress((void**)&w4l, g_w4l);
    cudaGetSymbolAddress((void**)&y1h, g_y1h); cudaGetSymbolAddress((void**)&y1l, g_y1l);
    cudaGetSymbolAddress((void**)&y2h, g_y2h); cudaGetSymbolAddress((void**)&y2l, g_y2l);
    cudaGetSymbolAddress((void**)&y3h, g_y3h); cudaGetSymbolAddress((void**)&y3l, g_y3l);

    cudaFuncSetAttribute(gemm_mma<true,  false>, cudaFuncAttributeMaxDynamicSharedMemorySize, GEMM_SMEM);
    cudaFuncSetAttribute(gemm_mma<false, true >, cudaFuncAttributeMaxDynamicSharedMemorySize, GEMM_SMEM);

    // 1) input projection (fp32, [T,B])
    proj_kernel<<<dim3((T_ + 31) / 32, B_ / 32), 256>>>(x, W_ih, b_ih, b_hh);
    // 2) recurrence -> g_hs [T,B], hidden (t = T_-1) -> out tail
    scan_kernel<<<B_ / 128, 128>>>(h0, W_hh, hid);
    // 3) transpose hs -> [B,TPAD] bf16 hi/lo
    transpose_hs<<<dim3(TPAD / 32, B_ / 32), 256>>>();
    // 4) weight conversions
    cvt_w<<<(D1_ * T_  + 255) / 256, 256>>>(w1, w1h, w1l, D1_, T_,  TPAD);
    cvt_w<<<(D2_ * D1_ + 255) / 256, 256>>>(w2, w2h, w2l, D2_, D1_, D1_);
    cvt_w<<<(D3_ * D2_ + 255) / 256, 256>>>(w3, w3h, w3l, D3_, D2_, D2_);
    cvt_w<<<(T_  * D3_ + 255) / 256, 256>>>(w4, w4h, w4l, T_,  D3_, D3_);

    // 5) y1 = relu(hsT @ w1^T + b1)   M=8192 N=1024 K=672
    gemm_mma<true, false><<<dim3(B_ / 128, D1_ / 128), 256, GEMM_SMEM>>>(
        ath, atl, w1h, w1l, b1, y1h, y1l, nullptr, TPAD, D1_, D1_);
    // 6) y2 = relu(y1 @ w2^T + b2)    K=1024
    gemm_mma<true, false><<<dim3(B_ / 128, D2_ / 128), 256, GEMM_SMEM>>>(
        y1h, y1l, w2h, w2l, b2, y2h, y2l, nullptr, D1_, D2_, D2_);
    // 7) y3 = relu(y2 @ w3^T + b3)    K=512
    gemm_mma<true, false><<<dim3(B_ / 128, D3_ / 128), 256, GEMM_SMEM>>>(
        y2h, y2l, w3h, w3l, b3, y3h, y3l, nullptr, D2_, D3_, D3_);
    // 8) out = y3 @ w4^T + b4         K=128, N=658 (masked)
    gemm_mma<false, true><<<dim3(B_ / 128, (T_ + 127) / 128), 256, GEMM_SMEM>>>(
        y3h, y3l, w4h, w4l, b4, nullptr, nullptr, out, D3_, T_, T_);
}